// round 1
// baseline (speedup 1.0000x reference)
#include <cuda_runtime.h>

#define NN 100000
#define INF_ 128
#define OUTF 64
#define NE 1600000

// Scratch for support = X @ W  (25.6 MB, static device global per harness rules)
__device__ float g_support[(size_t)NN * OUTF];

// ---------------------------------------------------------------------------
// Kernel 0: out[n, f] = bias[f]   (vectorized float4 broadcast)
// ---------------------------------------------------------------------------
__global__ void init_out_kernel(const float* __restrict__ bias,
                                float4* __restrict__ out4) {
    int i = blockIdx.x * blockDim.x + threadIdx.x;
    const int total4 = NN * OUTF / 4;  // 1.6M
    if (i < total4) {
        const float4* b4 = (const float4*)bias;  // 16 float4s of bias
        out4[i] = b4[i & 15];
    }
}

// ---------------------------------------------------------------------------
// Kernel 1: support = X @ W.  Tiled fp32 GEMM, BM=64, BN=64, BK=128 (full K),
// 256 threads, 4x4 register tile per thread.
// ---------------------------------------------------------------------------
__global__ __launch_bounds__(256, 2)
void gemm_kernel(const float* __restrict__ x, const float* __restrict__ w, int n) {
    __shared__ float xs[64][132];   // +4 pad (keeps 16B align: 132*4 % 16 == 0)
    __shared__ float ws[128][68];   // +4 pad

    const int tid  = threadIdx.x;
    const int brow = blockIdx.x * 64;

    // Load W [128,64] -> ws  (2048 float4s, 8 per thread)
#pragma unroll
    for (int it = 0; it < 8; it++) {
        int i = tid + it * 256;
        int k = i >> 4;
        int c = (i & 15) << 2;
        float4 v = *(const float4*)&w[k * OUTF + c];
        *(float4*)&ws[k][c] = v;
    }
    // Load X tile [64,128] -> xs (2048 float4s, 8 per thread), zero-pad tail rows
#pragma unroll
    for (int it = 0; it < 8; it++) {
        int i = tid + it * 256;
        int r = i >> 5;
        int k = (i & 31) << 2;
        int grow = brow + r;
        float4 v = make_float4(0.f, 0.f, 0.f, 0.f);
        if (grow < n) v = *(const float4*)&x[(size_t)grow * INF_ + k];
        *(float4*)&xs[r][k] = v;
    }
    __syncthreads();

    const int r0 = (tid >> 4) << 2;   // 0..60
    const int c0 = (tid & 15) << 2;   // 0..60

    float acc[4][4] = {};
#pragma unroll 4
    for (int k = 0; k < 128; k++) {
        float a0 = xs[r0 + 0][k];
        float a1 = xs[r0 + 1][k];
        float a2 = xs[r0 + 2][k];
        float a3 = xs[r0 + 3][k];
        float4 b = *(float4*)&ws[k][c0];
        acc[0][0] += a0 * b.x; acc[0][1] += a0 * b.y; acc[0][2] += a0 * b.z; acc[0][3] += a0 * b.w;
        acc[1][0] += a1 * b.x; acc[1][1] += a1 * b.y; acc[1][2] += a1 * b.z; acc[1][3] += a1 * b.w;
        acc[2][0] += a2 * b.x; acc[2][1] += a2 * b.y; acc[2][2] += a2 * b.z; acc[2][3] += a2 * b.w;
        acc[3][0] += a3 * b.x; acc[3][1] += a3 * b.y; acc[3][2] += a3 * b.z; acc[3][3] += a3 * b.w;
    }

#pragma unroll
    for (int i = 0; i < 4; i++) {
        int grow = brow + r0 + i;
        if (grow < n) {
            float4 v = make_float4(acc[i][0], acc[i][1], acc[i][2], acc[i][3]);
            *(float4*)&g_support[(size_t)grow * OUTF + c0] = v;
        }
    }
}

// ---------------------------------------------------------------------------
// Kernel 2: COO scatter.  One warp per edge: 32 lanes x float2 = 64 features.
// Coalesced float2 gather from support[edge_col], coalesced scalar atomics
// into out[edge_row]. Both buffers are L2-resident (25.6 MB each).
// ---------------------------------------------------------------------------
__global__ __launch_bounds__(256)
void scatter_kernel(const int* __restrict__ erow, const int* __restrict__ ecol,
                    const float* __restrict__ evals, float* __restrict__ out) {
    int gid = blockIdx.x * blockDim.x + threadIdx.x;
    int e = gid >> 5;
    if (e >= NE) return;
    int f = (gid & 31) << 1;          // 0,2,...,62

    int c = ecol[e];                  // broadcast within warp (same addr)
    int r = erow[e];
    float v = evals[e];

    float2 s = *(const float2*)&g_support[(size_t)c * OUTF + f];
    float* dst = &out[(size_t)r * OUTF + f];
    atomicAdd(dst + 0, s.x * v);
    atomicAdd(dst + 1, s.y * v);
}

// ---------------------------------------------------------------------------
extern "C" void kernel_launch(void* const* d_in, const int* in_sizes, int n_in,
                              void* d_out, int out_size) {
    const float* x     = (const float*)d_in[0];   // [100000,128]
    const float* w     = (const float*)d_in[1];   // [128,64]
    const float* bias  = (const float*)d_in[2];   // [64]
    const int*   erow  = (const int*)  d_in[3];   // [1.6M]
    const int*   ecol  = (const int*)  d_in[4];   // [1.6M]
    const float* evals = (const float*)d_in[5];   // [1.6M]
    float* out = (float*)d_out;                   // [100000,64]

    const int n = in_sizes[0] / INF_;             // 100000

    // out = bias (broadcast)
    {
        int total4 = n * OUTF / 4;
        init_out_kernel<<<(total4 + 255) / 256, 256>>>(bias, (float4*)out);
    }
    // support = X @ W
    {
        int blocks = (n + 63) / 64;
        gemm_kernel<<<blocks, 256>>>(x, w, n);
    }
    // out += segment_sum(support[ecol] * evals, erow)
    {
        long long threads = (long long)NE * 32;
        int blocks = (int)((threads + 255) / 256);
        scatter_kernel<<<blocks, 256>>>(erow, ecol, evals, out);
    }
}

// round 2
// speedup vs baseline: 1.6337x; 1.6337x over previous
#include <cuda_runtime.h>

#define NN 100000
#define INF_ 128
#define OUTF 64
#define NE 1600000

// Scratch for support = X @ W  (25.6 MB, static device global per harness rules)
__device__ float g_support[(size_t)NN * OUTF];

// ---------------------------------------------------------------------------
// Kernel 0: out[n, f] = bias[f]   (vectorized float4 broadcast)
// ---------------------------------------------------------------------------
__global__ void init_out_kernel(const float* __restrict__ bias,
                                float4* __restrict__ out4) {
    int i = blockIdx.x * blockDim.x + threadIdx.x;
    const int total4 = NN * OUTF / 4;  // 1.6M
    if (i < total4) {
        const float4* b4 = (const float4*)bias;  // 16 float4s of bias
        out4[i] = b4[i & 15];
    }
}

// ---------------------------------------------------------------------------
// Kernel 1: support = X @ W.  Tiled fp32 GEMM, BM=64, BN=64, BK=128 (full K),
// 256 threads, 4x4 register tile per thread.
// ---------------------------------------------------------------------------
__global__ __launch_bounds__(256, 2)
void gemm_kernel(const float* __restrict__ x, const float* __restrict__ w, int n) {
    __shared__ float xs[64][132];   // +4 pad (keeps 16B align: 132*4 % 16 == 0)
    __shared__ float ws[128][68];   // +4 pad

    const int tid  = threadIdx.x;
    const int brow = blockIdx.x * 64;

    // Load W [128,64] -> ws  (2048 float4s, 8 per thread)
#pragma unroll
    for (int it = 0; it < 8; it++) {
        int i = tid + it * 256;
        int k = i >> 4;
        int c = (i & 15) << 2;
        float4 v = *(const float4*)&w[k * OUTF + c];
        *(float4*)&ws[k][c] = v;
    }
    // Load X tile [64,128] -> xs (2048 float4s, 8 per thread), zero-pad tail rows
#pragma unroll
    for (int it = 0; it < 8; it++) {
        int i = tid + it * 256;
        int r = i >> 5;
        int k = (i & 31) << 2;
        int grow = brow + r;
        float4 v = make_float4(0.f, 0.f, 0.f, 0.f);
        if (grow < n) v = *(const float4*)&x[(size_t)grow * INF_ + k];
        *(float4*)&xs[r][k] = v;
    }
    __syncthreads();

    const int r0 = (tid >> 4) << 2;   // 0..60
    const int c0 = (tid & 15) << 2;   // 0..60

    float acc[4][4] = {};
#pragma unroll 4
    for (int k = 0; k < 128; k++) {
        float a0 = xs[r0 + 0][k];
        float a1 = xs[r0 + 1][k];
        float a2 = xs[r0 + 2][k];
        float a3 = xs[r0 + 3][k];
        float4 b = *(float4*)&ws[k][c0];
        acc[0][0] += a0 * b.x; acc[0][1] += a0 * b.y; acc[0][2] += a0 * b.z; acc[0][3] += a0 * b.w;
        acc[1][0] += a1 * b.x; acc[1][1] += a1 * b.y; acc[1][2] += a1 * b.z; acc[1][3] += a1 * b.w;
        acc[2][0] += a2 * b.x; acc[2][1] += a2 * b.y; acc[2][2] += a2 * b.z; acc[2][3] += a2 * b.w;
        acc[3][0] += a3 * b.x; acc[3][1] += a3 * b.y; acc[3][2] += a3 * b.z; acc[3][3] += a3 * b.w;
    }

#pragma unroll
    for (int i = 0; i < 4; i++) {
        int grow = brow + r0 + i;
        if (grow < n) {
            float4 v = make_float4(acc[i][0], acc[i][1], acc[i][2], acc[i][3]);
            *(float4*)&g_support[(size_t)grow * OUTF + c0] = v;
        }
    }
}

// ---------------------------------------------------------------------------
// Kernel 2: COO scatter.  16 threads per edge: each lane handles one float4
// (4 features).  Gather = 1x LDG.128 per lane (fully coalesced 256B/edge),
// scatter = 1x red.global.add.v4.f32 per lane (sm_90+ vector reduction).
// Both support and out are L2-resident (25.6 MB each).
// ---------------------------------------------------------------------------
__global__ __launch_bounds__(256)
void scatter_kernel(const int* __restrict__ erow, const int* __restrict__ ecol,
                    const float* __restrict__ evals, float* __restrict__ out) {
    long long gid = (long long)blockIdx.x * blockDim.x + threadIdx.x;
    int e = (int)(gid >> 4);
    if (e >= NE) return;
    int f = ((int)gid & 15) << 2;     // 0,4,...,60

    int c = __ldg(&ecol[e]);          // broadcast within 16-lane group
    int r = __ldg(&erow[e]);
    float v = __ldg(&evals[e]);

    float4 s = __ldg((const float4*)&g_support[(size_t)c * OUTF + f]);
    float4 g = make_float4(s.x * v, s.y * v, s.z * v, s.w * v);

    float* dst = &out[(size_t)r * OUTF + f];
    asm volatile("red.global.add.v4.f32 [%0], {%1, %2, %3, %4};"
                 :: "l"(dst), "f"(g.x), "f"(g.y), "f"(g.z), "f"(g.w)
                 : "memory");
}

// ---------------------------------------------------------------------------
extern "C" void kernel_launch(void* const* d_in, const int* in_sizes, int n_in,
                              void* d_out, int out_size) {
    const float* x     = (const float*)d_in[0];   // [100000,128]
    const float* w     = (const float*)d_in[1];   // [128,64]
    const float* bias  = (const float*)d_in[2];   // [64]
    const int*   erow  = (const int*)  d_in[3];   // [1.6M]
    const int*   ecol  = (const int*)  d_in[4];   // [1.6M]
    const float* evals = (const float*)d_in[5];   // [1.6M]
    float* out = (float*)d_out;                   // [100000,64]

    const int n = in_sizes[0] / INF_;             // 100000

    // out = bias (broadcast)
    {
        int total4 = n * OUTF / 4;
        init_out_kernel<<<(total4 + 255) / 256, 256>>>(bias, (float4*)out);
    }
    // support = X @ W
    {
        int blocks = (n + 63) / 64;
        gemm_kernel<<<blocks, 256>>>(x, w, n);
    }
    // out += segment_sum(support[ecol] * evals, erow)
    {
        long long threads = (long long)NE * 16;
        int blocks = (int)((threads + 255) / 256);
        scatter_kernel<<<blocks, 256>>>(erow, ecol, evals, out);
    }
}